// round 2
// baseline (speedup 1.0000x reference)
#include <cuda_runtime.h>

// out[i] = gen_map[x_gen[i]] + c * x_max_clock_speed[i] + d * x_max_tdp[i]
// Inputs (metadata order):
//  0: x_gen  int32 [N]
//  1: x_ix   int32 [N]         (unused)
//  2: x_max_clock_speed f32 [N]
//  3: x_max_tdp         f32 [N]
//  4: gen_map f32 [1024]
//  5: b f32 scalar (unused)
//  6: c f32 scalar
//  7: d f32 scalar

__global__ void __launch_bounds__(256) fused_gather_axpy(
    const int4* __restrict__ x_gen4,
    const float4* __restrict__ cs4,
    const float4* __restrict__ tdp4,
    const float* __restrict__ gen_map,
    const float* __restrict__ c_p,
    const float* __restrict__ d_p,
    float4* __restrict__ out4,
    int n4)
{
    int i = blockIdx.x * blockDim.x + threadIdx.x;
    if (i >= n4) return;

    const float c = __ldg(c_p);
    const float d = __ldg(d_p);

    int4  g = __ldg(&x_gen4[i]);
    float4 s = __ldg(&cs4[i]);
    float4 t = __ldg(&tdp4[i]);

    float4 o;
    o.x = __ldg(&gen_map[g.x]) + c * s.x + d * t.x;
    o.y = __ldg(&gen_map[g.y]) + c * s.y + d * t.y;
    o.z = __ldg(&gen_map[g.z]) + c * s.z + d * t.z;
    o.w = __ldg(&gen_map[g.w]) + c * s.w + d * t.w;

    out4[i] = o;
}

// Tail handler for N not divisible by 4 (not expected here, but safe).
__global__ void fused_gather_axpy_tail(
    const int* __restrict__ x_gen,
    const float* __restrict__ cs,
    const float* __restrict__ tdp,
    const float* __restrict__ gen_map,
    const float* __restrict__ c_p,
    const float* __restrict__ d_p,
    float* __restrict__ out,
    int start, int n)
{
    int i = start + blockIdx.x * blockDim.x + threadIdx.x;
    if (i >= n) return;
    float c = __ldg(c_p);
    float d = __ldg(d_p);
    out[i] = __ldg(&gen_map[x_gen[i]]) + c * cs[i] + d * tdp[i];
}

extern "C" void kernel_launch(void* const* d_in, const int* in_sizes, int n_in,
                              void* d_out, int out_size)
{
    const int*   x_gen   = (const int*)d_in[0];
    // d_in[1] = x_ix (unused)
    const float* cs      = (const float*)d_in[2];
    const float* tdp     = (const float*)d_in[3];
    const float* gen_map = (const float*)d_in[4];
    // d_in[5] = b (unused)
    const float* c_p     = (const float*)d_in[6];
    const float* d_p     = (const float*)d_in[7];
    float* out = (float*)d_out;

    const int n  = in_sizes[0];
    const int n4 = n / 4;

    if (n4 > 0) {
        int threads = 256;
        int blocks = (n4 + threads - 1) / threads;
        fused_gather_axpy<<<blocks, threads>>>(
            (const int4*)x_gen, (const float4*)cs, (const float4*)tdp,
            gen_map, c_p, d_p, (float4*)out, n4);
    }
    int rem_start = n4 * 4;
    if (rem_start < n) {
        int rem = n - rem_start;
        fused_gather_axpy_tail<<<(rem + 255) / 256, 256>>>(
            x_gen, cs, tdp, gen_map, c_p, d_p, out, rem_start, n);
    }
}

// round 3
// speedup vs baseline: 1.0770x; 1.0770x over previous
#include <cuda_runtime.h>

// out[i] = gen_map[x_gen[i]] + c * x_max_clock_speed[i] + d * x_max_tdp[i]
// N = 8388608, gen_map is 1024 floats (4 KB -> shared memory).
//
// Strategy: gen_map staged in smem (kills L1tex gather-replay pressure),
// 2x float4 per thread for MLP, streaming load/store hints on touch-once data.

#define BLOCK 256
#define VPT 2  // float4 groups per thread

__global__ void __launch_bounds__(BLOCK) fused_gather_axpy_smem(
    const int4* __restrict__ x_gen4,
    const float4* __restrict__ cs4,
    const float4* __restrict__ tdp4,
    const float* __restrict__ gen_map,
    const float* __restrict__ c_p,
    const float* __restrict__ d_p,
    float4* __restrict__ out4,
    int n4)
{
    __shared__ float s_map[1024];

    // Cooperative load of gen_map: 256 threads x 4 floats (float4 each)
    {
        float4 m = __ldg(&((const float4*)gen_map)[threadIdx.x]);
        ((float4*)s_map)[threadIdx.x] = m;
    }

    const float c = __ldg(c_p);
    const float d = __ldg(d_p);

    __syncthreads();

    const int base = blockIdx.x * (BLOCK * VPT) + threadIdx.x;

    // Front-batch all global loads (MLP = 6) before any dependent work.
    int4   g[VPT];
    float4 s[VPT];
    float4 t[VPT];
#pragma unroll
    for (int v = 0; v < VPT; v++) {
        int i = base + v * BLOCK;
        if (i < n4) {
            g[v] = __ldcs(&x_gen4[i]);
            s[v] = __ldcs(&cs4[i]);
            t[v] = __ldcs(&tdp4[i]);
        }
    }

#pragma unroll
    for (int v = 0; v < VPT; v++) {
        int i = base + v * BLOCK;
        if (i < n4) {
            float4 o;
            o.x = s_map[g[v].x] + c * s[v].x + d * t[v].x;
            o.y = s_map[g[v].y] + c * s[v].y + d * t[v].y;
            o.z = s_map[g[v].z] + c * s[v].z + d * t[v].z;
            o.w = s_map[g[v].w] + c * s[v].w + d * t[v].w;
            __stcs(&out4[i], o);
        }
    }
}

// Tail handler for N not divisible by 4 (not expected here, but safe).
__global__ void fused_gather_axpy_tail(
    const int* __restrict__ x_gen,
    const float* __restrict__ cs,
    const float* __restrict__ tdp,
    const float* __restrict__ gen_map,
    const float* __restrict__ c_p,
    const float* __restrict__ d_p,
    float* __restrict__ out,
    int start, int n)
{
    int i = start + blockIdx.x * blockDim.x + threadIdx.x;
    if (i >= n) return;
    float c = __ldg(c_p);
    float d = __ldg(d_p);
    out[i] = __ldg(&gen_map[x_gen[i]]) + c * cs[i] + d * tdp[i];
}

extern "C" void kernel_launch(void* const* d_in, const int* in_sizes, int n_in,
                              void* d_out, int out_size)
{
    const int*   x_gen   = (const int*)d_in[0];
    // d_in[1] = x_ix (unused)
    const float* cs      = (const float*)d_in[2];
    const float* tdp     = (const float*)d_in[3];
    const float* gen_map = (const float*)d_in[4];
    // d_in[5] = b (unused)
    const float* c_p     = (const float*)d_in[6];
    const float* d_p     = (const float*)d_in[7];
    float* out = (float*)d_out;

    const int n  = in_sizes[0];
    const int n4 = n / 4;

    if (n4 > 0) {
        int elems_per_block = BLOCK * VPT;
        int blocks = (n4 + elems_per_block - 1) / elems_per_block;
        fused_gather_axpy_smem<<<blocks, BLOCK>>>(
            (const int4*)x_gen, (const float4*)cs, (const float4*)tdp,
            gen_map, c_p, d_p, (float4*)out, n4);
    }
    int rem_start = n4 * 4;
    if (rem_start < n) {
        int rem = n - rem_start;
        fused_gather_axpy_tail<<<(rem + 255) / 256, 256>>>(
            x_gen, cs, tdp, gen_map, c_p, d_p, out, rem_start, n);
    }
}